// round 16
// baseline (speedup 1.0000x reference)
#include <cuda_runtime.h>
#include <math.h>

#define NN 50000
#define NE 1600000
#define NG 64
#define NB 196   // (NN+255)/256
#define CAP 96   // bucket capacity per node (deg ~ Bin(1.6M, 1/50K): 11 sigma)

// ---------------- device scratch ----------------
__device__ int   g_is64;
__device__ __align__(256) float g_xl[NN * 64];
__device__ __align__(256) float g_xr[NN * 64];
__device__ __align__(256) float g_h [NN * 64];
__device__ int   g_wp [NN];
__device__ int   g_csr[NN * CAP];

// Combined: zero g_wp + detect int64 vs int32 edge_index.
__global__ void k_init(const void* ei) {
    int i = blockIdx.x * blockDim.x + threadIdx.x;
    if (i < NN) g_wp[i] = 0;
    if (i == 0) {
        const int* p = (const int*)ei;
        int nz = 0;
        #pragma unroll 4
        for (int j = 0; j < 128; j++) nz |= p[2 * j + 1];
        g_is64 = (nz == 0) ? 1 : 0;
    }
}

// Bucketed scatter: 2 edges per thread, no hist/scan needed.
__global__ void k_scatter(const void* ei) {
    int i = (blockIdx.x * blockDim.x + threadIdx.x) * 2;
    if (i >= NE) return;
    int s0, s1, d0, d1;
    if (g_is64) {
        longlong2 vs = *(const longlong2*)((const long long*)ei + i);
        longlong2 vd = *(const longlong2*)((const long long*)ei + NE + i);
        s0 = (int)vs.x; s1 = (int)vs.y; d0 = (int)vd.x; d1 = (int)vd.y;
    } else {
        int2 vs = *(const int2*)((const int*)ei + i);
        int2 vd = *(const int2*)((const int*)ei + NE + i);
        s0 = vs.x; s1 = vs.y; d0 = vd.x; d1 = vd.y;
    }
    int p0 = atomicAdd(&g_wp[d0], 1); g_csr[d0 * CAP + p0] = s0;
    int p1 = atomicAdd(&g_wp[d1], 1); g_csr[d1 * CAP + p1] = s1;
}

// Fused dual GEMM: Yl = X@Wl, Yr = X@Wr. 256 threads, 128 rows/block,
// each thread 4 rows x 8 cols x 2 outputs. Padded x stride K+4.
template<int K>
__global__ void __launch_bounds__(256, 1)
k_gemmF(const float* __restrict__ X, const float* __restrict__ Wl,
        const float* __restrict__ Wr, float* __restrict__ Yl,
        float* __restrict__ Yr) {
    extern __shared__ float sm[];
    const int KP = K + 4;
    float* Wsl = sm;                  // K*64
    float* Wsr = sm + K * 64;         // K*64
    float* xs  = sm + 2 * K * 64;     // 128*(K+4)
    int tid = threadIdx.x;
    int n0  = blockIdx.x * 128;
    for (int i = tid; i < K * 16; i += 256) {
        ((float4*)Wsl)[i] = ((const float4*)Wl)[i];
        ((float4*)Wsr)[i] = ((const float4*)Wr)[i];
    }
    for (int i = tid; i < 32 * K; i += 256) {
        int r = i / (K / 4), kk = i % (K / 4);
        int row = n0 + r;
        float4 v = (row < NN) ? ((const float4*)X)[(size_t)row * (K / 4) + kk]
                              : make_float4(0.f, 0.f, 0.f, 0.f);
        *(float4*)&xs[r * KP + kk * 4] = v;
    }
    __syncthreads();
    int n = tid >> 3, c0 = (tid & 7) * 8;
    float al[32], ar[32];
    #pragma unroll
    for (int i = 0; i < 32; i++) { al[i] = 0.f; ar[i] = 0.f; }
    for (int k = 0; k < K; k++) {
        float4 l0 = *(const float4*)&Wsl[k * 64 + c0];
        float4 l1 = *(const float4*)&Wsl[k * 64 + c0 + 4];
        float4 r0 = *(const float4*)&Wsr[k * 64 + c0];
        float4 r1 = *(const float4*)&Wsr[k * 64 + c0 + 4];
        #pragma unroll
        for (int r = 0; r < 4; r++) {
            float xv = xs[(n + r * 32) * KP + k];
            al[r*8+0] += xv*l0.x; al[r*8+1] += xv*l0.y;
            al[r*8+2] += xv*l0.z; al[r*8+3] += xv*l0.w;
            al[r*8+4] += xv*l1.x; al[r*8+5] += xv*l1.y;
            al[r*8+6] += xv*l1.z; al[r*8+7] += xv*l1.w;
            ar[r*8+0] += xv*r0.x; ar[r*8+1] += xv*r0.y;
            ar[r*8+2] += xv*r0.z; ar[r*8+3] += xv*r0.w;
            ar[r*8+4] += xv*r1.x; ar[r*8+5] += xv*r1.y;
            ar[r*8+6] += xv*r1.z; ar[r*8+7] += xv*r1.w;
        }
    }
    #pragma unroll
    for (int r = 0; r < 4; r++) {
        int row = n0 + n + r * 32;
        if (row < NN) {
            float4* yl = (float4*)&Yl[(size_t)row * 64 + c0];
            yl[0] = make_float4(al[r*8+0], al[r*8+1], al[r*8+2], al[r*8+3]);
            yl[1] = make_float4(al[r*8+4], al[r*8+5], al[r*8+6], al[r*8+7]);
            float4* yr = (float4*)&Yr[(size_t)row * 64 + c0];
            yr[0] = make_float4(ar[r*8+0], ar[r*8+1], ar[r*8+2], ar[r*8+3]);
            yr[1] = make_float4(ar[r*8+4], ar[r*8+5], ar[r*8+6], ar[r*8+7]);
        }
    }
}

// Fused GATv2: one warp per dst node, 4 edges/iteration (8-lane quarters),
// fixed-base softmax (base = self-loop score). Bucketed CSR (stride CAP).
// Score uses the exact identity lrelu(a) = 0.6a + 0.4|a| with the per-dst
// constant 0.6*att.xr[d] dropped (cancels in softmax):
//   score_eff = sum_c 0.6*att_c*v_c + 0.4*att_c*|v_c + xr_c|
// -> per channel: FADD + 2x FFMA (|.| is a free operand modifier), no FSEL.
template<int NH>
__global__ void __launch_bounds__(128)
k_gat(const float4* __restrict__ XL, const float4* __restrict__ XR,
      const float* __restrict__ att, const float* __restrict__ bias,
      float4* __restrict__ out) {
    int w    = (blockIdx.x * blockDim.x + threadIdx.x) >> 5;
    int lane = threadIdx.x & 31;
    if (w >= NN) return;
    const int d = w;
    const int qt = lane >> 3, li = lane & 7;
    const unsigned FULL = 0xffffffffu;

    float4 A0 = ((const float4*)att)[li];
    float4 A1 = ((const float4*)att)[8 + li];
    float4 a60 = make_float4(0.6f*A0.x, 0.6f*A0.y, 0.6f*A0.z, 0.6f*A0.w);
    float4 a40 = make_float4(0.4f*A0.x, 0.4f*A0.y, 0.4f*A0.z, 0.4f*A0.w);
    float4 a61 = make_float4(0.6f*A1.x, 0.6f*A1.y, 0.6f*A1.z, 0.6f*A1.w);
    float4 a41 = make_float4(0.4f*A1.x, 0.4f*A1.y, 0.4f*A1.z, 0.4f*A1.w);
    float4 xr0 = XR[(size_t)d * 16 + li];
    float4 xr1 = XR[(size_t)d * 16 + 8 + li];

    float base0, base1;
    float ssum0 = 0.f, ssum1 = 0.f;
    float4 acc0 = make_float4(0.f, 0.f, 0.f, 0.f);
    float4 acc1 = make_float4(0.f, 0.f, 0.f, 0.f);

#define SCORE(v0, v1, P0, P1)                                                 \
    {                                                                         \
        float pa = a60.x * (v0).x + a40.x * fabsf((v0).x + xr0.x);            \
        pa += a60.y * (v0).y + a40.y * fabsf((v0).y + xr0.y);                 \
        pa += a60.z * (v0).z + a40.z * fabsf((v0).z + xr0.z);                 \
        pa += a60.w * (v0).w + a40.w * fabsf((v0).w + xr0.w);                 \
        float pb = a61.x * (v1).x + a41.x * fabsf((v1).x + xr1.x);            \
        pb += a61.y * (v1).y + a41.y * fabsf((v1).y + xr1.y);                 \
        pb += a61.z * (v1).z + a41.z * fabsf((v1).z + xr1.z);                 \
        pb += a61.w * (v1).w + a41.w * fabsf((v1).w + xr1.w);                 \
        if (NH == 1) {                                                        \
            float p = pa + pb;                                                \
            p += __shfl_xor_sync(FULL, p, 1);                                 \
            p += __shfl_xor_sync(FULL, p, 2);                                 \
            p += __shfl_xor_sync(FULL, p, 4);                                 \
            P0 = p; P1 = p;                                                   \
        } else {                                                              \
            float u = (li & 1) ? pb : pa;                                     \
            float t = (li & 1) ? pa : pb;                                     \
            u += __shfl_xor_sync(FULL, t, 1);                                 \
            u += __shfl_xor_sync(FULL, u, 2);                                 \
            u += __shfl_xor_sync(FULL, u, 4);                                 \
            float o = __shfl_xor_sync(FULL, u, 1);                            \
            P0 = (li & 1) ? o : u;                                            \
            P1 = (li & 1) ? u : o;                                            \
        }                                                                     \
    }

    // self loop: all quarters compute score (identical); quarter 0 contributes
    {
        float4 s0 = XL[(size_t)d * 16 + li];
        float4 s1 = XL[(size_t)d * 16 + 8 + li];
        float p0, p1;
        SCORE(s0, s1, p0, p1);
        base0 = p0; base1 = p1;
        float e = (qt == 0) ? 1.f : 0.f;   // exp(p - base) = 1
        ssum0 = e; ssum1 = e;
        acc0 = make_float4(e * s0.x, e * s0.y, e * s0.z, e * s0.w);
        acc1 = make_float4(e * s1.x, e * s1.y, e * s1.z, e * s1.w);
    }

    const int deg  = g_wp[d];
    const int base = d * CAP;
    for (int j = 0; j < deg; j += 32) {
        int cnt = min(32, deg - j);
        int sv = (j + lane < deg) ? g_csr[base + j + lane] : d;
        if (cnt == 32) {
            #pragma unroll 2
            for (int k = 0; k < 32; k += 4) {
                int s = __shfl_sync(FULL, sv, k + qt);
                float4 v0 = XL[(size_t)s * 16 + li];
                float4 v1 = XL[(size_t)s * 16 + 8 + li];
                float p0, p1;
                SCORE(v0, v1, p0, p1);
                float e0 = __expf(p0 - base0);
                float e1 = (NH == 2) ? __expf(p1 - base1) : e0;
                ssum0 += e0; ssum1 += e1;
                acc0.x += e0 * v0.x; acc0.y += e0 * v0.y;
                acc0.z += e0 * v0.z; acc0.w += e0 * v0.w;
                acc1.x += e1 * v1.x; acc1.y += e1 * v1.y;
                acc1.z += e1 * v1.z; acc1.w += e1 * v1.w;
            }
        } else {
            for (int k = 0; k < cnt; k += 4) {
                int idx = k + qt;
                int s = __shfl_sync(FULL, sv, idx & 31);
                bool valid = idx < cnt;
                float4 v0 = XL[(size_t)(valid ? s : d) * 16 + li];
                float4 v1 = XL[(size_t)(valid ? s : d) * 16 + 8 + li];
                float p0, p1;
                SCORE(v0, v1, p0, p1);
                float e0 = valid ? __expf(p0 - base0) : 0.f;
                float e1 = (NH == 2) ? (valid ? __expf(p1 - base1) : 0.f) : e0;
                ssum0 += e0; ssum1 += e1;
                acc0.x += e0 * v0.x; acc0.y += e0 * v0.y;
                acc0.z += e0 * v0.z; acc0.w += e0 * v0.w;
                acc1.x += e1 * v1.x; acc1.y += e1 * v1.y;
                acc1.z += e1 * v1.z; acc1.w += e1 * v1.w;
            }
        }
    }
#undef SCORE

    // merge quarters (xor 8, 16)
#define MRG(x) { x += __shfl_xor_sync(FULL, x, 8); x += __shfl_xor_sync(FULL, x, 16); }
    MRG(ssum0)
    if (NH == 2) { MRG(ssum1) } else { ssum1 = ssum0; }
    MRG(acc0.x) MRG(acc0.y) MRG(acc0.z) MRG(acc0.w)
    MRG(acc1.x) MRG(acc1.y) MRG(acc1.z) MRG(acc1.w)
#undef MRG

    if (qt == 0) {
        float inv0 = 1.f / (ssum0 + 1e-16f);
        float inv1 = 1.f / (ssum1 + 1e-16f);
        float4 bi0 = ((const float4*)bias)[li];
        float4 bi1 = ((const float4*)bias)[8 + li];
        float4 o0, o1;
        o0.x = acc0.x * inv0 + bi0.x; o0.y = acc0.y * inv0 + bi0.y;
        o0.z = acc0.z * inv0 + bi0.z; o0.w = acc0.w * inv0 + bi0.w;
        o1.x = acc1.x * inv1 + bi1.x; o1.y = acc1.y * inv1 + bi1.y;
        o1.z = acc1.z * inv1 + bi1.z; o1.w = acc1.w * inv1 + bi1.w;
        o0.x = o0.x > 0.f ? o0.x : expm1f(o0.x);
        o0.y = o0.y > 0.f ? o0.y : expm1f(o0.y);
        o0.z = o0.z > 0.f ? o0.z : expm1f(o0.z);
        o0.w = o0.w > 0.f ? o0.w : expm1f(o0.w);
        o1.x = o1.x > 0.f ? o1.x : expm1f(o1.x);
        o1.y = o1.y > 0.f ? o1.y : expm1f(o1.y);
        o1.z = o1.z > 0.f ? o1.z : expm1f(o1.z);
        o1.w = o1.w > 0.f ? o1.w : expm1f(o1.w);
        out[(size_t)d * 16 + li]     = o0;
        out[(size_t)d * 16 + 8 + li] = o1;
    }
}

// Pool + classifier: one block per graph (batch sorted), no atomics.
__global__ void k_poolfin(const void* batch, const float* __restrict__ lw,
                          const float* __restrict__ lb, float* __restrict__ out) {
    __shared__ float sh[256];
    int g = blockIdx.x;
    int t = threadIdx.x;
    int is64 = g_is64;
    int lo = 0, hi = NN;
    while (lo < hi) {
        int mid = (lo + hi) >> 1;
        int b = is64 ? (int)((const long long*)batch)[mid] : ((const int*)batch)[mid];
        if (b < g) lo = mid + 1; else hi = mid;
    }
    int lo2 = lo, hi2 = NN;
    while (lo2 < hi2) {
        int mid = (lo2 + hi2) >> 1;
        int b = is64 ? (int)((const long long*)batch)[mid] : ((const int*)batch)[mid];
        if (b < g + 1) lo2 = mid + 1; else hi2 = mid;
    }
    int beg = lo, endn = lo2;
    int c = t & 63, r0 = t >> 6;
    float acc = 0.f;
    for (int n = beg + r0; n < endn; n += 4) acc += g_h[(size_t)n * 64 + c];
    sh[t] = acc;
    __syncthreads();
    if (t < 64) {
        float s = sh[t] + sh[t + 64] + sh[t + 128] + sh[t + 192];
        float cnt = (float)(endn - beg);
        cnt = cnt > 1.f ? cnt : 1.f;
        sh[t] = s / cnt;
    }
    __syncthreads();
    if (t < 2) {
        float s = 0.f;
        #pragma unroll 8
        for (int c2 = 0; c2 < 64; c2++) s += sh[c2] * lw[c2 * 2 + t];
        out[g * 2 + t] = s + lb[t];
    }
}

extern "C" void kernel_launch(void* const* d_in, const int* in_sizes, int n_in,
                              void* d_out, int out_size) {
    const float* x     = (const float*)d_in[0];
    const void*  ei    = d_in[1];
    const void*  batch = d_in[2];
    const float* Wl1   = (const float*)d_in[3];
    const float* Wr1   = (const float*)d_in[4];
    const float* att1  = (const float*)d_in[5];
    const float* b1    = (const float*)d_in[6];
    const float* Wl2   = (const float*)d_in[7];
    const float* Wr2   = (const float*)d_in[8];
    const float* att2  = (const float*)d_in[9];
    const float* b2    = (const float*)d_in[10];
    const float* lw    = (const float*)d_in[11];
    const float* lb    = (const float*)d_in[12];
    float* out = (float*)d_out;

    float *xl, *xr, *h;
    cudaGetSymbolAddress((void**)&xl, g_xl);
    cudaGetSymbolAddress((void**)&xr, g_xr);
    cudaGetSymbolAddress((void**)&h,  g_h);

    const int TB = 256;
    const int GB_E2   = (NE / 2 + TB - 1) / TB;  // 3125
    const int GB_GAT  = (NN + 3) / 4;            // 12500 (128-thread blocks)
    const int GB_GEMM = (NN + 127) / 128;        // 391

    const int SMF128 = (2 * 128 * 64 + 128 * (128 + 4)) * 4;  // 133120
    const int SMF64  = (2 * 64 * 64 + 128 * (64 + 4)) * 4;    // 67584
    cudaFuncSetAttribute(k_gemmF<128>, cudaFuncAttributeMaxDynamicSharedMemorySize, SMF128);
    cudaFuncSetAttribute(k_gemmF<64>,  cudaFuncAttributeMaxDynamicSharedMemorySize, SMF64);

    // Fork: layer-1 dual GEMM on a side stream, overlapped with the (scan-free)
    // bucketed CSR build on the main stream. Host objects only.
    cudaStream_t s2;
    cudaStreamCreateWithFlags(&s2, cudaStreamNonBlocking);
    cudaEvent_t e0, e1;
    cudaEventCreateWithFlags(&e0, cudaEventDisableTiming);
    cudaEventCreateWithFlags(&e1, cudaEventDisableTiming);

    cudaEventRecord(e0, 0);
    cudaStreamWaitEvent(s2, e0, 0);
    k_gemmF<128><<<GB_GEMM, TB, SMF128, s2>>>(x, Wl1, Wr1, xl, xr);
    cudaEventRecord(e1, s2);

    // Bucketed CSR build on main stream (overlapped with the GEMM above)
    k_init<<<NB, TB>>>(ei);
    k_scatter<<<GB_E2, TB>>>(ei);

    // Join: gat<2> needs both CSR and xl/xr
    cudaStreamWaitEvent(0, e1, 0);

    // ---- layer 1 (heads=2, ch=32) ----
    k_gat<2><<<GB_GAT, 128>>>((const float4*)xl, (const float4*)xr, att1, b1, (float4*)h);

    // ---- layer 2 (heads=1, ch=64) ----
    k_gemmF<64><<<GB_GEMM, TB, SMF64>>>(h, Wl2, Wr2, xl, xr);
    k_gat<1><<<GB_GAT, 128>>>((const float4*)xl, (const float4*)xr, att2, b2, (float4*)h);

    // ---- pooling + classifier ----
    k_poolfin<<<NG, 256>>>(batch, lw, lb, out);
}

// round 17
// speedup vs baseline: 1.0414x; 1.0414x over previous
#include <cuda_runtime.h>
#include <math.h>

#define NN 50000
#define NE 1600000
#define NG 64
#define NB 196   // (NN+255)/256
#define CAP 96   // bucket capacity per node (deg ~ Bin(1.6M, 1/50K): 11 sigma)

// ---------------- device scratch ----------------
__device__ int   g_is64;
__device__ __align__(256) float g_xl[NN * 64];
__device__ __align__(256) float g_xr[NN * 64];
__device__ __align__(256) float g_h [NN * 64];
__device__ int   g_wp [NN];
__device__ int   g_csr[NN * CAP];

// Combined: zero g_wp + detect int64 vs int32 edge_index.
__global__ void k_init(const void* ei) {
    int i = blockIdx.x * blockDim.x + threadIdx.x;
    if (i < NN) g_wp[i] = 0;
    if (i == 0) {
        const int* p = (const int*)ei;
        int nz = 0;
        #pragma unroll 4
        for (int j = 0; j < 128; j++) nz |= p[2 * j + 1];
        g_is64 = (nz == 0) ? 1 : 0;
    }
}

// Bucketed scatter: 2 edges per thread, no hist/scan needed.
__global__ void k_scatter(const void* ei) {
    int i = (blockIdx.x * blockDim.x + threadIdx.x) * 2;
    if (i >= NE) return;
    int s0, s1, d0, d1;
    if (g_is64) {
        longlong2 vs = *(const longlong2*)((const long long*)ei + i);
        longlong2 vd = *(const longlong2*)((const long long*)ei + NE + i);
        s0 = (int)vs.x; s1 = (int)vs.y; d0 = (int)vd.x; d1 = (int)vd.y;
    } else {
        int2 vs = *(const int2*)((const int*)ei + i);
        int2 vd = *(const int2*)((const int*)ei + NE + i);
        s0 = vs.x; s1 = vs.y; d0 = vd.x; d1 = vd.y;
    }
    int p0 = atomicAdd(&g_wp[d0], 1); g_csr[d0 * CAP + p0] = s0;
    int p1 = atomicAdd(&g_wp[d1], 1); g_csr[d1 * CAP + p1] = s1;
}

// Fused dual GEMM: Yl = X@Wl, Yr = X@Wr. 256 threads, 128 rows/block,
// each thread 4 rows x 8 cols x 2 outputs. Padded x stride K+4.
template<int K>
__global__ void __launch_bounds__(256, 1)
k_gemmF(const float* __restrict__ X, const float* __restrict__ Wl,
        const float* __restrict__ Wr, float* __restrict__ Yl,
        float* __restrict__ Yr) {
    extern __shared__ float sm[];
    const int KP = K + 4;
    float* Wsl = sm;                  // K*64
    float* Wsr = sm + K * 64;         // K*64
    float* xs  = sm + 2 * K * 64;     // 128*(K+4)
    int tid = threadIdx.x;
    int n0  = blockIdx.x * 128;
    for (int i = tid; i < K * 16; i += 256) {
        ((float4*)Wsl)[i] = ((const float4*)Wl)[i];
        ((float4*)Wsr)[i] = ((const float4*)Wr)[i];
    }
    for (int i = tid; i < 32 * K; i += 256) {
        int r = i / (K / 4), kk = i % (K / 4);
        int row = n0 + r;
        float4 v = (row < NN) ? ((const float4*)X)[(size_t)row * (K / 4) + kk]
                              : make_float4(0.f, 0.f, 0.f, 0.f);
        *(float4*)&xs[r * KP + kk * 4] = v;
    }
    __syncthreads();
    int n = tid >> 3, c0 = (tid & 7) * 8;
    float al[32], ar[32];
    #pragma unroll
    for (int i = 0; i < 32; i++) { al[i] = 0.f; ar[i] = 0.f; }
    for (int k = 0; k < K; k++) {
        float4 l0 = *(const float4*)&Wsl[k * 64 + c0];
        float4 l1 = *(const float4*)&Wsl[k * 64 + c0 + 4];
        float4 r0 = *(const float4*)&Wsr[k * 64 + c0];
        float4 r1 = *(const float4*)&Wsr[k * 64 + c0 + 4];
        #pragma unroll
        for (int r = 0; r < 4; r++) {
            float xv = xs[(n + r * 32) * KP + k];
            al[r*8+0] += xv*l0.x; al[r*8+1] += xv*l0.y;
            al[r*8+2] += xv*l0.z; al[r*8+3] += xv*l0.w;
            al[r*8+4] += xv*l1.x; al[r*8+5] += xv*l1.y;
            al[r*8+6] += xv*l1.z; al[r*8+7] += xv*l1.w;
            ar[r*8+0] += xv*r0.x; ar[r*8+1] += xv*r0.y;
            ar[r*8+2] += xv*r0.z; ar[r*8+3] += xv*r0.w;
            ar[r*8+4] += xv*r1.x; ar[r*8+5] += xv*r1.y;
            ar[r*8+6] += xv*r1.z; ar[r*8+7] += xv*r1.w;
        }
    }
    #pragma unroll
    for (int r = 0; r < 4; r++) {
        int row = n0 + n + r * 32;
        if (row < NN) {
            float4* yl = (float4*)&Yl[(size_t)row * 64 + c0];
            yl[0] = make_float4(al[r*8+0], al[r*8+1], al[r*8+2], al[r*8+3]);
            yl[1] = make_float4(al[r*8+4], al[r*8+5], al[r*8+6], al[r*8+7]);
            float4* yr = (float4*)&Yr[(size_t)row * 64 + c0];
            yr[0] = make_float4(ar[r*8+0], ar[r*8+1], ar[r*8+2], ar[r*8+3]);
            yr[1] = make_float4(ar[r*8+4], ar[r*8+5], ar[r*8+6], ar[r*8+7]);
        }
    }
}

// Fused GATv2: one warp per dst node, 4 edges/iteration (8-lane quarters),
// fixed-base softmax (base = self-loop score). Bucketed CSR (stride CAP).
// Score: lrelu(a) = 0.6a + 0.4|a|; per-dst constant 0.6*att.xr[d] cancels in
// softmax, so score_eff = sum_c 0.6*att_c * ( v_c + (2/3)*|v_c + xr_c| ).
// Per channel: FADD + FFMA-imm + FFMA — 3 fma-pipe ops, no FSEL, and the only
// score constants are at6 = 0.6*att (8 regs, same as plain att).
template<int NH>
__global__ void __launch_bounds__(128)
k_gat(const float4* __restrict__ XL, const float4* __restrict__ XR,
      const float* __restrict__ att, const float* __restrict__ bias,
      float4* __restrict__ out) {
    int w    = (blockIdx.x * blockDim.x + threadIdx.x) >> 5;
    int lane = threadIdx.x & 31;
    if (w >= NN) return;
    const int d = w;
    const int qt = lane >> 3, li = lane & 7;
    const unsigned FULL = 0xffffffffu;
    const float TT = 0.66666667f;   // 2/3: 0.6*(2/3) = 0.4

    float4 A0 = ((const float4*)att)[li];
    float4 A1 = ((const float4*)att)[8 + li];
    float4 at6 = make_float4(0.6f*A0.x, 0.6f*A0.y, 0.6f*A0.z, 0.6f*A0.w);
    float4 at7 = make_float4(0.6f*A1.x, 0.6f*A1.y, 0.6f*A1.z, 0.6f*A1.w);
    float4 xr0 = XR[(size_t)d * 16 + li];
    float4 xr1 = XR[(size_t)d * 16 + 8 + li];

    float base0, base1;
    float ssum0 = 0.f, ssum1 = 0.f;
    float4 acc0 = make_float4(0.f, 0.f, 0.f, 0.f);
    float4 acc1 = make_float4(0.f, 0.f, 0.f, 0.f);

#define SCORE(v0, v1, P0, P1)                                                 \
    {                                                                         \
        float pa, pb;                                                         \
        {                                                                     \
            float t0 = fmaf(TT, fabsf((v0).x + xr0.x), (v0).x);               \
            float t1 = fmaf(TT, fabsf((v0).y + xr0.y), (v0).y);               \
            float t2 = fmaf(TT, fabsf((v0).z + xr0.z), (v0).z);               \
            float t3 = fmaf(TT, fabsf((v0).w + xr0.w), (v0).w);               \
            pa = at6.x*t0 + at6.y*t1 + at6.z*t2 + at6.w*t3;                   \
        }                                                                     \
        {                                                                     \
            float t0 = fmaf(TT, fabsf((v1).x + xr1.x), (v1).x);               \
            float t1 = fmaf(TT, fabsf((v1).y + xr1.y), (v1).y);               \
            float t2 = fmaf(TT, fabsf((v1).z + xr1.z), (v1).z);               \
            float t3 = fmaf(TT, fabsf((v1).w + xr1.w), (v1).w);               \
            pb = at7.x*t0 + at7.y*t1 + at7.z*t2 + at7.w*t3;                   \
        }                                                                     \
        if (NH == 1) {                                                        \
            float p = pa + pb;                                                \
            p += __shfl_xor_sync(FULL, p, 1);                                 \
            p += __shfl_xor_sync(FULL, p, 2);                                 \
            p += __shfl_xor_sync(FULL, p, 4);                                 \
            P0 = p; P1 = p;                                                   \
        } else {                                                              \
            float u = (li & 1) ? pb : pa;                                     \
            float t = (li & 1) ? pa : pb;                                     \
            u += __shfl_xor_sync(FULL, t, 1);                                 \
            u += __shfl_xor_sync(FULL, u, 2);                                 \
            u += __shfl_xor_sync(FULL, u, 4);                                 \
            float o = __shfl_xor_sync(FULL, u, 1);                            \
            P0 = (li & 1) ? o : u;                                            \
            P1 = (li & 1) ? u : o;                                            \
        }                                                                     \
    }

    // self loop: all quarters compute score (identical); quarter 0 contributes
    {
        float4 s0 = XL[(size_t)d * 16 + li];
        float4 s1 = XL[(size_t)d * 16 + 8 + li];
        float p0, p1;
        SCORE(s0, s1, p0, p1);
        base0 = p0; base1 = p1;
        float e = (qt == 0) ? 1.f : 0.f;   // exp(p - base) = 1
        ssum0 = e; ssum1 = e;
        acc0 = make_float4(e * s0.x, e * s0.y, e * s0.z, e * s0.w);
        acc1 = make_float4(e * s1.x, e * s1.y, e * s1.z, e * s1.w);
    }

    const int deg  = g_wp[d];
    const int base = d * CAP;
    for (int j = 0; j < deg; j += 32) {
        int cnt = min(32, deg - j);
        int sv = (j + lane < deg) ? g_csr[base + j + lane] : d;
        if (cnt == 32) {
            #pragma unroll 2
            for (int k = 0; k < 32; k += 4) {
                int s = __shfl_sync(FULL, sv, k + qt);
                float4 v0 = XL[(size_t)s * 16 + li];
                float4 v1 = XL[(size_t)s * 16 + 8 + li];
                float p0, p1;
                SCORE(v0, v1, p0, p1);
                float e0 = __expf(p0 - base0);
                float e1 = (NH == 2) ? __expf(p1 - base1) : e0;
                ssum0 += e0; ssum1 += e1;
                acc0.x += e0 * v0.x; acc0.y += e0 * v0.y;
                acc0.z += e0 * v0.z; acc0.w += e0 * v0.w;
                acc1.x += e1 * v1.x; acc1.y += e1 * v1.y;
                acc1.z += e1 * v1.z; acc1.w += e1 * v1.w;
            }
        } else {
            for (int k = 0; k < cnt; k += 4) {
                int idx = k + qt;
                int s = __shfl_sync(FULL, sv, idx & 31);
                bool valid = idx < cnt;
                float4 v0 = XL[(size_t)(valid ? s : d) * 16 + li];
                float4 v1 = XL[(size_t)(valid ? s : d) * 16 + 8 + li];
                float p0, p1;
                SCORE(v0, v1, p0, p1);
                float e0 = valid ? __expf(p0 - base0) : 0.f;
                float e1 = (NH == 2) ? (valid ? __expf(p1 - base1) : 0.f) : e0;
                ssum0 += e0; ssum1 += e1;
                acc0.x += e0 * v0.x; acc0.y += e0 * v0.y;
                acc0.z += e0 * v0.z; acc0.w += e0 * v0.w;
                acc1.x += e1 * v1.x; acc1.y += e1 * v1.y;
                acc1.z += e1 * v1.z; acc1.w += e1 * v1.w;
            }
        }
    }
#undef SCORE

    // merge quarters (xor 8, 16)
#define MRG(x) { x += __shfl_xor_sync(FULL, x, 8); x += __shfl_xor_sync(FULL, x, 16); }
    MRG(ssum0)
    if (NH == 2) { MRG(ssum1) } else { ssum1 = ssum0; }
    MRG(acc0.x) MRG(acc0.y) MRG(acc0.z) MRG(acc0.w)
    MRG(acc1.x) MRG(acc1.y) MRG(acc1.z) MRG(acc1.w)
#undef MRG

    if (qt == 0) {
        float inv0 = 1.f / (ssum0 + 1e-16f);
        float inv1 = 1.f / (ssum1 + 1e-16f);
        float4 bi0 = ((const float4*)bias)[li];
        float4 bi1 = ((const float4*)bias)[8 + li];
        float4 o0, o1;
        o0.x = acc0.x * inv0 + bi0.x; o0.y = acc0.y * inv0 + bi0.y;
        o0.z = acc0.z * inv0 + bi0.z; o0.w = acc0.w * inv0 + bi0.w;
        o1.x = acc1.x * inv1 + bi1.x; o1.y = acc1.y * inv1 + bi1.y;
        o1.z = acc1.z * inv1 + bi1.z; o1.w = acc1.w * inv1 + bi1.w;
        o0.x = o0.x > 0.f ? o0.x : expm1f(o0.x);
        o0.y = o0.y > 0.f ? o0.y : expm1f(o0.y);
        o0.z = o0.z > 0.f ? o0.z : expm1f(o0.z);
        o0.w = o0.w > 0.f ? o0.w : expm1f(o0.w);
        o1.x = o1.x > 0.f ? o1.x : expm1f(o1.x);
        o1.y = o1.y > 0.f ? o1.y : expm1f(o1.y);
        o1.z = o1.z > 0.f ? o1.z : expm1f(o1.z);
        o1.w = o1.w > 0.f ? o1.w : expm1f(o1.w);
        out[(size_t)d * 16 + li]     = o0;
        out[(size_t)d * 16 + 8 + li] = o1;
    }
}

// Pool + classifier: one block per graph (batch sorted), no atomics.
__global__ void k_poolfin(const void* batch, const float* __restrict__ lw,
                          const float* __restrict__ lb, float* __restrict__ out) {
    __shared__ float sh[256];
    int g = blockIdx.x;
    int t = threadIdx.x;
    int is64 = g_is64;
    int lo = 0, hi = NN;
    while (lo < hi) {
        int mid = (lo + hi) >> 1;
        int b = is64 ? (int)((const long long*)batch)[mid] : ((const int*)batch)[mid];
        if (b < g) lo = mid + 1; else hi = mid;
    }
    int lo2 = lo, hi2 = NN;
    while (lo2 < hi2) {
        int mid = (lo2 + hi2) >> 1;
        int b = is64 ? (int)((const long long*)batch)[mid] : ((const int*)batch)[mid];
        if (b < g + 1) lo2 = mid + 1; else hi2 = mid;
    }
    int beg = lo, endn = lo2;
    int c = t & 63, r0 = t >> 6;
    float acc = 0.f;
    for (int n = beg + r0; n < endn; n += 4) acc += g_h[(size_t)n * 64 + c];
    sh[t] = acc;
    __syncthreads();
    if (t < 64) {
        float s = sh[t] + sh[t + 64] + sh[t + 128] + sh[t + 192];
        float cnt = (float)(endn - beg);
        cnt = cnt > 1.f ? cnt : 1.f;
        sh[t] = s / cnt;
    }
    __syncthreads();
    if (t < 2) {
        float s = 0.f;
        #pragma unroll 8
        for (int c2 = 0; c2 < 64; c2++) s += sh[c2] * lw[c2 * 2 + t];
        out[g * 2 + t] = s + lb[t];
    }
}

extern "C" void kernel_launch(void* const* d_in, const int* in_sizes, int n_in,
                              void* d_out, int out_size) {
    const float* x     = (const float*)d_in[0];
    const void*  ei    = d_in[1];
    const void*  batch = d_in[2];
    const float* Wl1   = (const float*)d_in[3];
    const float* Wr1   = (const float*)d_in[4];
    const float* att1  = (const float*)d_in[5];
    const float* b1    = (const float*)d_in[6];
    const float* Wl2   = (const float*)d_in[7];
    const float* Wr2   = (const float*)d_in[8];
    const float* att2  = (const float*)d_in[9];
    const float* b2    = (const float*)d_in[10];
    const float* lw    = (const float*)d_in[11];
    const float* lb    = (const float*)d_in[12];
    float* out = (float*)d_out;

    float *xl, *xr, *h;
    cudaGetSymbolAddress((void**)&xl, g_xl);
    cudaGetSymbolAddress((void**)&xr, g_xr);
    cudaGetSymbolAddress((void**)&h,  g_h);

    const int TB = 256;
    const int GB_E2   = (NE / 2 + TB - 1) / TB;  // 3125
    const int GB_GAT  = (NN + 3) / 4;            // 12500 (128-thread blocks)
    const int GB_GEMM = (NN + 127) / 128;        // 391

    const int SMF128 = (2 * 128 * 64 + 128 * (128 + 4)) * 4;  // 133120
    const int SMF64  = (2 * 64 * 64 + 128 * (64 + 4)) * 4;    // 67584
    cudaFuncSetAttribute(k_gemmF<128>, cudaFuncAttributeMaxDynamicSharedMemorySize, SMF128);
    cudaFuncSetAttribute(k_gemmF<64>,  cudaFuncAttributeMaxDynamicSharedMemorySize, SMF64);

    // Fork: layer-1 dual GEMM on a side stream, overlapped with the (scan-free)
    // bucketed CSR build on the main stream. Host objects only.
    cudaStream_t s2;
    cudaStreamCreateWithFlags(&s2, cudaStreamNonBlocking);
    cudaEvent_t e0, e1;
    cudaEventCreateWithFlags(&e0, cudaEventDisableTiming);
    cudaEventCreateWithFlags(&e1, cudaEventDisableTiming);

    cudaEventRecord(e0, 0);
    cudaStreamWaitEvent(s2, e0, 0);
    k_gemmF<128><<<GB_GEMM, TB, SMF128, s2>>>(x, Wl1, Wr1, xl, xr);
    cudaEventRecord(e1, s2);

    // Bucketed CSR build on main stream (overlapped with the GEMM above)
    k_init<<<NB, TB>>>(ei);
    k_scatter<<<GB_E2, TB>>>(ei);

    // Join: gat<2> needs both CSR and xl/xr
    cudaStreamWaitEvent(0, e1, 0);

    // ---- layer 1 (heads=2, ch=32) ----
    k_gat<2><<<GB_GAT, 128>>>((const float4*)xl, (const float4*)xr, att1, b1, (float4*)h);

    // ---- layer 2 (heads=1, ch=64) ----
    k_gemmF<64><<<GB_GEMM, TB, SMF64>>>(h, Wl2, Wr2, xl, xr);
    k_gat<1><<<GB_GAT, 128>>>((const float4*)xl, (const float4*)xr, att2, b2, (float4*)h);

    // ---- pooling + classifier ----
    k_poolfin<<<NG, 256>>>(batch, lw, lb, out);
}